// round 8
// baseline (speedup 1.0000x reference)
#include <cuda_runtime.h>
#include <cuda_bf16.h>

// EdgeToVertex: tril(x) * 257x257 "plus" kernel, stride (256,1), SAME
// -> out [512, 1, 256, 1].
//
// out[b,w] = colsum(w)                 colsum(w) = sum_{r=w..255} x[b,r,w]
//          + S                          S = sum_{c=0..128} x[b,128,c]
//          - 2*x[b,128,w]     (w<=128)
//          - prefix128(w-129) (w>=129)
//
// R8: R6 structure + __ldcs streaming loads (read-once data; don't pollute
// L1/L2). Grid (4,512); CTA (blk,b) covers 64 rows. Thread t owns float4
// column group c4 = t&63 over 16 rows: 16 predicated LDG.128.LU, smem reduce
// over 4 row groups, 256 REDG per CTA. blk==2 CTA adds the row-128
// prefix-scan correction (cached re-read).

#define NN 256
#define NB 512
#define RB 64
#define NBLK (NN / RB)     // 4
#define RPT 16             // rows per thread

__global__ __launch_bounds__(256) void etv_zero(float* __restrict__ out) {
    out[blockIdx.x * NN + threadIdx.x] = 0.0f;
}

__global__ __launch_bounds__(256) void etv_main(const float* __restrict__ x,
                                                float* __restrict__ out) {
    const int blk = blockIdx.x;            // row block 0..3 (64 rows each)
    const int b   = blockIdx.y;            // batch
    const int t   = threadIdx.x;
    const int c4     = t & 63;             // column group (cols 4c4..4c4+3)
    const int rowOff = t >> 6;             // 0..3 -> 16 rows each
    const int r0  = blk * RB + rowOff * RPT;
    const int cbase = c4 * 4;
    const float* __restrict__ X = x + (size_t)b * (NN * NN);
    const float* p = X + r0 * NN + cbase;

    float4 acc = make_float4(0.f, 0.f, 0.f, 0.f);

    #pragma unroll
    for (int i = 0; i < RPT; ++i) {
        const int r = r0 + i;
        if (cbase <= r) {                  // at least one component in tril
            float4 v = __ldcs(reinterpret_cast<const float4*>(p + i * NN));
            const int d = r - cbase;       // 0..3 => straddles the diagonal
            if (d < 3) {
                if (d < 1) v.y = 0.f;
                if (d < 2) v.z = 0.f;
                v.w = 0.f;
            }
            acc.x += v.x; acc.y += v.y; acc.z += v.z; acc.w += v.w;
        }
    }

    // Reduce the 4 row groups per column group.
    __shared__ float4 part[4][64];
    part[rowOff][c4] = acc;

    // blk==2 owns row 128: hoist its cached re-read before the barrier.
    float myv = 0.f;
    if (blk == 2 && t <= 128) myv = X[128 * NN + t];
    __syncthreads();

    if (t < 64) {
        float4 s = part[0][t];
        #pragma unroll
        for (int j = 1; j < 4; ++j) {
            float4 p4 = part[j][t];
            s.x += p4.x; s.y += p4.y; s.z += p4.z; s.w += p4.w;
        }
        const int lastrow = blk * RB + RB - 1;
        float* o = &out[b * NN + t * 4];
        if (t * 4     <= lastrow) atomicAdd(o + 0, s.x);
        if (t * 4 + 1 <= lastrow) atomicAdd(o + 1, s.y);
        if (t * 4 + 2 <= lastrow) atomicAdd(o + 2, s.z);
        if (t * 4 + 3 <= lastrow) atomicAdd(o + 3, s.w);
    }

    if (blk != 2) return;

    // Row-128 prefix-scan correction.
    __shared__ float sdata[NN];
    const int w = t;
    sdata[w] = myv;                        // myv==0 for w>128
    __syncthreads();

    #pragma unroll
    for (int off = 1; off < NN; off <<= 1) {
        float tv = (w >= off) ? sdata[w - off] : 0.f;
        __syncthreads();
        sdata[w] += tv;
        __syncthreads();
    }

    const float S = sdata[128];
    const float corr = (w <= 128) ? (S - 2.0f * myv) : (S - sdata[w - 129]);
    atomicAdd(&out[b * NN + w], corr);
}

extern "C" void kernel_launch(void* const* d_in, const int* in_sizes, int n_in,
                              void* d_out, int out_size) {
    const float* x = (const float*)d_in[0];
    if (n_in > 1 && in_sizes[0] != NB * NN * NN) {
        for (int i = 0; i < n_in; ++i) {
            if (in_sizes[i] == NB * NN * NN) { x = (const float*)d_in[i]; break; }
        }
    }
    float* out = (float*)d_out;

    etv_zero<<<NB, NN>>>(out);
    dim3 g(NBLK, NB);
    etv_main<<<g, NN>>>(x, out);
}

// round 9
// speedup vs baseline: 1.1372x; 1.1372x over previous
#include <cuda_runtime.h>
#include <cuda_bf16.h>

// EdgeToVertex: tril(x) * 257x257 "plus" kernel, stride (256,1), SAME
// -> out [512, 1, 256, 1].
//
// out[b,w] = colsum(w)                 colsum(w) = sum_{r=w..255} x[b,r,w]
//          + S                          S = sum_{c=0..128} x[b,128,c]
//          - 2*x[b,128,w]     (w<=128)
//          - prefix128(w-129) (w>=129)
//
// R9: exact R6 structure (best so far), plus heavy-first CTA ordering:
// grid (NB, NBLK) with blk = NBLK-1-blockIdx.y so the 7x-heavier bottom row
// blocks launch in the first wave and the near-empty top blocks form the
// tail. CTA (blk,b) covers 64 rows; thread t owns float4 column group
// c4 = t&63 over 16 rows: 16 predicated LDG.128 (MLP 16), smem reduce over
// 4 row groups, 256 REDG per CTA. blk==2 CTA adds the row-128 prefix-scan
// correction (its re-read of row 128 is a cache hit).

#define NN 256
#define NB 512
#define RB 64
#define NBLK (NN / RB)     // 4
#define RPT 16             // rows per thread

__global__ __launch_bounds__(256) void etv_zero(float* __restrict__ out) {
    out[blockIdx.x * NN + threadIdx.x] = 0.0f;
}

__global__ __launch_bounds__(256) void etv_main(const float* __restrict__ x,
                                                float* __restrict__ out) {
    const int blk = (NBLK - 1) - blockIdx.y;   // heavy blocks (large blk) first
    const int b   = blockIdx.x;                // batch
    const int t   = threadIdx.x;
    const int c4     = t & 63;             // column group (cols 4c4..4c4+3)
    const int rowOff = t >> 6;             // 0..3 -> 16 rows each
    const int r0  = blk * RB + rowOff * RPT;
    const int cbase = c4 * 4;
    const float* __restrict__ X = x + (size_t)b * (NN * NN);
    const float* p = X + r0 * NN + cbase;

    float4 acc = make_float4(0.f, 0.f, 0.f, 0.f);

    #pragma unroll
    for (int i = 0; i < RPT; ++i) {
        const int r = r0 + i;
        if (cbase <= r) {                  // at least one component in tril
            float4 v = *reinterpret_cast<const float4*>(p + i * NN);
            const int d = r - cbase;       // 0..3 => straddles the diagonal
            if (d < 3) {
                if (d < 1) v.y = 0.f;
                if (d < 2) v.z = 0.f;
                v.w = 0.f;
            }
            acc.x += v.x; acc.y += v.y; acc.z += v.z; acc.w += v.w;
        }
    }

    // Reduce the 4 row groups per column group.
    __shared__ float4 part[4][64];
    part[rowOff][c4] = acc;
    __syncthreads();

    if (t < 64) {
        float4 s = part[0][t];
        #pragma unroll
        for (int j = 1; j < 4; ++j) {
            float4 p4 = part[j][t];
            s.x += p4.x; s.y += p4.y; s.z += p4.z; s.w += p4.w;
        }
        const int lastrow = blk * RB + RB - 1;
        float* o = &out[b * NN + t * 4];
        if (t * 4     <= lastrow) atomicAdd(o + 0, s.x);
        if (t * 4 + 1 <= lastrow) atomicAdd(o + 1, s.y);
        if (t * 4 + 2 <= lastrow) atomicAdd(o + 2, s.z);
        if (t * 4 + 3 <= lastrow) atomicAdd(o + 3, s.w);
    }

    if (blk != 2) return;

    // blk == 2 owns row 128: prefix-scan correction (row re-read = cache hit).
    __shared__ float sdata[NN];
    const int w = t;
    const float myv = (w <= 128) ? X[128 * NN + w] : 0.f;
    sdata[w] = myv;
    __syncthreads();

    #pragma unroll
    for (int off = 1; off < NN; off <<= 1) {
        float tv = (w >= off) ? sdata[w - off] : 0.f;
        __syncthreads();
        sdata[w] += tv;
        __syncthreads();
    }

    const float S = sdata[128];
    const float corr = (w <= 128) ? (S - 2.0f * myv) : (S - sdata[w - 129]);
    atomicAdd(&out[b * NN + w], corr);
}

extern "C" void kernel_launch(void* const* d_in, const int* in_sizes, int n_in,
                              void* d_out, int out_size) {
    const float* x = (const float*)d_in[0];
    if (n_in > 1 && in_sizes[0] != NB * NN * NN) {
        for (int i = 0; i < n_in; ++i) {
            if (in_sizes[i] == NB * NN * NN) { x = (const float*)d_in[i]; break; }
        }
    }
    float* out = (float*)d_out;

    etv_zero<<<NB, NN>>>(out);
    dim3 g(NB, NBLK);
    etv_main<<<g, NN>>>(x, out);
}